// round 9
// baseline (speedup 1.0000x reference)
#include <cuda_runtime.h>
#include <math.h>

// Problem constants
#define Bk   4
#define Ck   256
#define BNk  64
#define Hk   128
#define Wk   128
#define HWk  16384
#define K2k  9

// -------- scratch (device globals; no allocations allowed) --------
__device__ float g_z   [Bk * BNk * HWk];   // down-proj output
__device__ float g_off [Bk * 18  * HWk];   // offsets
__device__ float g_mask[Bk * 9   * HWk];   // sigmoid(mask)
__device__ float g_dwT [Ck * BNk];         // down_w transposed: [c][o]
__device__ float g_wbT [BNk * 9 * 32];     // off/mask weights: [(ic*9+tap)*32 + oc], oc<27 valid
__device__ float g_wbBias[32];             // 18 off_b + 9 mask_b + pad
__device__ float g_wdT [9 * BNk * BNk];    // def_w: [(k*64+c)*64 + o]
__device__ float g_sum [Ck];
__device__ float g_sumsq[Ck];

// -------- prep: transpose/repack weights, zero stats --------
__global__ void prep_kernel(const float* __restrict__ down_w,
                            const float* __restrict__ off_w,
                            const float* __restrict__ off_b,
                            const float* __restrict__ mask_w,
                            const float* __restrict__ mask_b,
                            const float* __restrict__ def_w) {
    int i = blockIdx.x * 256 + threadIdx.x;
    if (i < Ck) { g_sum[i] = 0.f; g_sumsq[i] = 0.f; }
    if (i < Ck * BNk) {                 // down_w [64][256] -> [c][o]
        int o = i >> 8, c = i & 255;
        g_dwT[c * 64 + o] = down_w[i];
    }
    if (i < BNk * 9 * 32) {             // off/mask weights
        int oc = i & 31; int rest = i >> 5;
        int tap = rest % 9, ic = rest / 9;
        float v = 0.f;
        if (oc < 18)      v = off_w [(oc * 64 + ic) * 9 + tap];
        else if (oc < 27) v = mask_w[((oc - 18) * 64 + ic) * 9 + tap];
        g_wbT[i] = v;
    }
    if (i < 32) {
        float v = 0.f;
        if (i < 18)      v = off_b[i];
        else if (i < 27) v = mask_b[i - 18];
        g_wbBias[i] = v;
    }
    if (i < BNk * BNk * 9) {            // def_w [o][c][k] -> [(k*64+c)*64+o]
        int o = i / 576, rem = i % 576, c = rem / 9, k = rem % 9;
        g_wdT[(k * 64 + c) * 64 + o] = def_w[i];
    }
}

// -------- kernel A: 1x1 down conv (256->64) --------
__global__ void __launch_bounds__(256) down_kernel(const float* __restrict__ x) {
    int pix = blockIdx.x * 256 + threadIdx.x;
    int b   = blockIdx.y;
    const float* xp = x + (size_t)b * Ck * HWk + pix;

    float acc[64];
#pragma unroll
    for (int o = 0; o < 64; o++) acc[o] = 0.f;

#pragma unroll 4
    for (int c = 0; c < Ck; c++) {
        float xv = __ldg(xp + (size_t)c * HWk);
        const float4* w4 = reinterpret_cast<const float4*>(g_dwT + c * 64);
#pragma unroll
        for (int j = 0; j < 16; j++) {
            float4 w = __ldg(w4 + j);
            acc[4*j+0] += w.x * xv;
            acc[4*j+1] += w.y * xv;
            acc[4*j+2] += w.z * xv;
            acc[4*j+3] += w.w * xv;
        }
    }
    float* zp = g_z + (size_t)b * BNk * HWk + pix;
#pragma unroll
    for (int o = 0; o < 64; o++) zp[(size_t)o * HWk] = acc[o];
}

// -------- kernel B: 3x3 conv -> offsets(18) + sigmoid(mask)(9) --------
__global__ void __launch_bounds__(128) offmask_kernel() {
    __shared__ float s[3][130];
    int tx = threadIdx.x;      // x coordinate
    int y  = blockIdx.x;       // row
    int b  = blockIdx.y;

    float acc[28];
#pragma unroll
    for (int j = 0; j < 28; j++) acc[j] = g_wbBias[j];

    const float* zb = g_z + (size_t)b * BNk * HWk;

#pragma unroll 1
    for (int ic = 0; ic < 64; ic++) {
        const float* zp = zb + (size_t)ic * HWk;
        __syncthreads();
#pragma unroll
        for (int dy = 0; dy < 3; dy++) {
            int yy = y + dy - 1;
            s[dy][tx + 1] = (yy >= 0 && yy < Hk) ? __ldg(zp + yy * Wk + tx) : 0.f;
        }
        if (tx == 0) {
            s[0][0] = 0.f; s[1][0] = 0.f; s[2][0] = 0.f;
            s[0][129] = 0.f; s[1][129] = 0.f; s[2][129] = 0.f;
        }
        __syncthreads();

        const float4* wrow = reinterpret_cast<const float4*>(g_wbT + ic * 9 * 32);
#pragma unroll
        for (int tap = 0; tap < 9; tap++) {
            int ky = tap / 3, kx = tap % 3;
            float zv = s[ky][tx + kx];
#pragma unroll
            for (int j = 0; j < 7; j++) {
                float4 w = __ldg(wrow + tap * 8 + j);
                acc[4*j+0] += w.x * zv;
                acc[4*j+1] += w.y * zv;
                acc[4*j+2] += w.z * zv;
                acc[4*j+3] += w.w * zv;
            }
        }
    }

    int p = y * Wk + tx;
    float* offp = g_off + (size_t)b * 18 * HWk + p;
#pragma unroll
    for (int j = 0; j < 18; j++) offp[(size_t)j * HWk] = acc[j];
    float* mp = g_mask + (size_t)b * 9 * HWk + p;
#pragma unroll
    for (int j = 0; j < 9; j++)
        mp[(size_t)j * HWk] = 1.f / (1.f + __expf(-acc[18 + j]));
}

// -------- kernel C: deform conv + 1x1 up + residual + BN stats --------
__global__ void __launch_bounds__(128) deform_kernel(const float* __restrict__ x,
                                                     const float* __restrict__ def_b,
                                                     const float* __restrict__ up_w,
                                                     float* __restrict__ out) {
    int tx = threadIdx.x;      // x coordinate (one row per block)
    int y  = blockIdx.x;
    int b  = blockIdx.y;
    int p  = y * Wk + tx;

    const float* zb   = g_z    + (size_t)b * BNk * HWk;
    const float* offp = g_off  + (size_t)b * 18  * HWk + p;
    const float* mp   = g_mask + (size_t)b * 9   * HWk + p;

    float acc[64];
#pragma unroll
    for (int o = 0; o < 64; o++) acc[o] = __ldg(def_b + o);

#pragma unroll 1
    for (int k = 0; k < 9; k++) {
        int ky = k / 3, kx = k % 3;
        float dy = __ldg(offp + (size_t)(2 * k)     * HWk);
        float dx = __ldg(offp + (size_t)(2 * k + 1) * HWk);
        float mk = __ldg(mp   + (size_t)k           * HWk);

        float py = dy + (float)(y  + ky - 1);
        float px = dx + (float)(tx + kx - 1);
        float y0f = floorf(py), x0f = floorf(px);
        float wy = py - y0f, wx = px - x0f;
        int y0 = (int)y0f, x0 = (int)x0f;
        int y1 = y0 + 1,   x1 = x0 + 1;
        bool vy0 = (y0 >= 0) && (y0 < Hk), vy1 = (y1 >= 0) && (y1 < Hk);
        bool vx0 = (x0 >= 0) && (x0 < Wk), vx1 = (x1 >= 0) && (x1 < Wk);
        float a00 = (1.f - wy) * (1.f - wx) * mk * ((vy0 && vx0) ? 1.f : 0.f);
        float a01 = (1.f - wy) * wx         * mk * ((vy0 && vx1) ? 1.f : 0.f);
        float a10 = wy         * (1.f - wx) * mk * ((vy1 && vx0) ? 1.f : 0.f);
        float a11 = wy         * wx         * mk * ((vy1 && vx1) ? 1.f : 0.f);
        int yc0 = min(max(y0, 0), Hk - 1), yc1 = min(max(y1, 0), Hk - 1);
        int xc0 = min(max(x0, 0), Wk - 1), xc1 = min(max(x1, 0), Wk - 1);
        int i00 = yc0 * Wk + xc0, i01 = yc0 * Wk + xc1;
        int i10 = yc1 * Wk + xc0, i11 = yc1 * Wk + xc1;

        const float* wk = g_wdT + k * 64 * 64;
#pragma unroll 2
        for (int c = 0; c < 64; c++) {
            const float* zc = zb + (size_t)c * HWk;
            float v = a00 * __ldg(zc + i00) + a01 * __ldg(zc + i01)
                    + a10 * __ldg(zc + i10) + a11 * __ldg(zc + i11);
            const float4* w4 = reinterpret_cast<const float4*>(wk + c * 64);
#pragma unroll
            for (int j = 0; j < 16; j++) {
                float4 w = __ldg(w4 + j);
                acc[4*j+0] += w.x * v;
                acc[4*j+1] += w.y * v;
                acc[4*j+2] += w.z * v;
                acc[4*j+3] += w.w * v;
            }
        }
    }

    // fused 1x1 up conv + residual + BN statistics
    const float* xp = x   + (size_t)b * Ck * HWk + p;
    float*       op = out + (size_t)b * Ck * HWk + p;
#pragma unroll 1
    for (int oc = 0; oc < Ck; oc++) {
        const float4* w4 = reinterpret_cast<const float4*>(up_w + oc * 64);
        float s0 = 0.f, s1 = 0.f, s2 = 0.f, s3 = 0.f;
#pragma unroll
        for (int j = 0; j < 16; j++) {
            float4 w = __ldg(w4 + j);
            s0 += w.x * acc[4*j+0];
            s1 += w.y * acc[4*j+1];
            s2 += w.z * acc[4*j+2];
            s3 += w.w * acc[4*j+3];
        }
        float yv = __ldg(xp + (size_t)oc * HWk) + ((s0 + s1) + (s2 + s3));
        op[(size_t)oc * HWk] = yv;

        float ws = yv, wq = yv * yv;
#pragma unroll
        for (int d = 16; d; d >>= 1) {
            ws += __shfl_xor_sync(0xffffffffu, ws, d);
            wq += __shfl_xor_sync(0xffffffffu, wq, d);
        }
        if ((tx & 31) == 0) {
            atomicAdd(&g_sum[oc], ws);
            atomicAdd(&g_sumsq[oc], wq);
        }
    }
}

// -------- kernel E: BatchNorm (training stats) + SiLU, in place --------
__global__ void __launch_bounds__(256) norm_kernel(float* __restrict__ out,
                                                   const float* __restrict__ gamma,
                                                   const float* __restrict__ beta) {
    const float invN = 1.f / (float)(Bk * HWk);   // 1/65536
    size_t i = (size_t)blockIdx.x * 256 + threadIdx.x;   // float4 index
    int ch = (int)((i >> 12) & 255);                      // 4096 float4 per channel

    float mean = g_sum[ch] * invN;
    float var  = g_sumsq[ch] * invN - mean * mean;
    float r    = rsqrtf(var + 1e-5f);
    float sc   = r * __ldg(gamma + ch);
    float sh   = __ldg(beta + ch) - mean * sc;

    float4* o4 = reinterpret_cast<float4*>(out);
    float4 v = o4[i];
    float h;
    h = v.x * sc + sh; v.x = h / (1.f + __expf(-h));
    h = v.y * sc + sh; v.y = h / (1.f + __expf(-h));
    h = v.z * sc + sh; v.z = h / (1.f + __expf(-h));
    h = v.w * sc + sh; v.w = h / (1.f + __expf(-h));
    o4[i] = v;
}

// -------- launch --------
extern "C" void kernel_launch(void* const* d_in, const int* in_sizes, int n_in,
                              void* d_out, int out_size) {
    const float* x      = (const float*)d_in[0];
    const float* down_w = (const float*)d_in[1];
    const float* off_w  = (const float*)d_in[2];
    const float* off_b  = (const float*)d_in[3];
    const float* mask_w = (const float*)d_in[4];
    const float* mask_b = (const float*)d_in[5];
    const float* def_w  = (const float*)d_in[6];
    const float* def_b  = (const float*)d_in[7];
    const float* up_w   = (const float*)d_in[8];
    const float* gamma  = (const float*)d_in[9];
    const float* beta   = (const float*)d_in[10];
    float* out = (float*)d_out;

    prep_kernel<<<144, 256>>>(down_w, off_w, off_b, mask_w, mask_b, def_w);
    down_kernel<<<dim3(HWk / 256, Bk), 256>>>(x);
    offmask_kernel<<<dim3(Hk, Bk), 128>>>();
    deform_kernel<<<dim3(Hk, Bk), 128>>>(x, def_b, up_w, out);
    norm_kernel<<<(Bk * Ck * HWk) / 4 / 256, 256>>>(out, gamma, beta);
}

// round 12
// speedup vs baseline: 1.8849x; 1.8849x over previous
#include <cuda_runtime.h>
#include <math.h>

// Problem constants
#define Bk   4
#define Ck   256
#define BNk  64
#define Hk   128
#define Wk   128
#define HWk  16384
#define K2k  9

// -------- scratch (device globals; no allocations allowed) --------
__device__ float g_z   [Bk * BNk * HWk];   // down-proj output (NCHW)
__device__ float g_d   [Bk * BNk * HWk];   // deform-conv output (NCHW)
__device__ float g_off [Bk * 18  * HWk];   // offsets
__device__ float g_mask[Bk * 9   * HWk];   // sigmoid(mask)
__device__ float g_dwT [Ck * BNk];         // down_w transposed: [c][o]
__device__ float g_wbT [BNk * 9 * 32];     // off/mask weights: [(ic*9+tap)*32 + oc], oc<27 valid
__device__ float g_wbBias[32];             // 18 off_b + 9 mask_b + pad
__device__ float g_wdT [9 * BNk * BNk];    // def_w: [(k*64+c)*64 + o]
__device__ float g_sum [Ck];
__device__ float g_sumsq[Ck];

// -------- prep: transpose/repack weights, zero stats --------
__global__ void prep_kernel(const float* __restrict__ down_w,
                            const float* __restrict__ off_w,
                            const float* __restrict__ off_b,
                            const float* __restrict__ mask_w,
                            const float* __restrict__ mask_b,
                            const float* __restrict__ def_w) {
    int i = blockIdx.x * 256 + threadIdx.x;
    if (i < Ck) { g_sum[i] = 0.f; g_sumsq[i] = 0.f; }
    if (i < Ck * BNk) {                 // down_w [64][256] -> [c][o]
        int o = i >> 8, c = i & 255;
        g_dwT[c * 64 + o] = down_w[i];
    }
    if (i < BNk * 9 * 32) {             // off/mask weights
        int oc = i & 31; int rest = i >> 5;
        int tap = rest % 9, ic = rest / 9;
        float v = 0.f;
        if (oc < 18)      v = off_w [(oc * 64 + ic) * 9 + tap];
        else if (oc < 27) v = mask_w[((oc - 18) * 64 + ic) * 9 + tap];
        g_wbT[i] = v;
    }
    if (i < 32) {
        float v = 0.f;
        if (i < 18)      v = off_b[i];
        else if (i < 27) v = mask_b[i - 18];
        g_wbBias[i] = v;
    }
    if (i < BNk * BNk * 9) {            // def_w [o][c][k] -> [(k*64+c)*64+o]
        int o = i / 576, rem = i % 576, c = rem / 9, k = rem % 9;
        g_wdT[(k * 64 + c) * 64 + o] = def_w[i];
    }
}

// -------- kernel A: 1x1 down conv (256->64), oc half-split, smem weights ----
__global__ void __launch_bounds__(256) down_kernel(const float* __restrict__ x) {
    __shared__ __align__(16) float wsm[64 * 64];   // 16KB: chunk of dwT [c][64 oc]
    int tid  = threadIdx.x;
    int half = tid >> 7;               // 0/1 -> oc range
    int lpx  = tid & 127;
    int gp   = blockIdx.x * 128 + lpx; // global pixel incl. batch
    int b    = gp >> 14;
    int p    = gp & 16383;

    const float* xp = x + (size_t)b * Ck * HWk + p;

    float acc[32];
#pragma unroll
    for (int o = 0; o < 32; o++) acc[o] = 0.f;

    for (int c0 = 0; c0 < Ck; c0 += 64) {
        __syncthreads();
        const float4* wsrc = reinterpret_cast<const float4*>(g_dwT + c0 * 64);
        float4* wdst = reinterpret_cast<float4*>(wsm);
#pragma unroll
        for (int j = tid; j < 1024; j += 256) wdst[j] = wsrc[j];
        __syncthreads();

#pragma unroll 4
        for (int ci = 0; ci < 64; ci++) {
            float xv = __ldg(xp + (size_t)(c0 + ci) * HWk);
            const float4* w4 = reinterpret_cast<const float4*>(wsm + ci * 64 + half * 32);
#pragma unroll
            for (int j = 0; j < 8; j++) {
                float4 w = w4[j];
                acc[4*j+0] += w.x * xv;
                acc[4*j+1] += w.y * xv;
                acc[4*j+2] += w.z * xv;
                acc[4*j+3] += w.w * xv;
            }
        }
    }
    float* zp = g_z + (size_t)b * BNk * HWk + (size_t)half * 32 * HWk + p;
#pragma unroll
    for (int o = 0; o < 32; o++) zp[(size_t)o * HWk] = acc[o];
}

// -------- kernel B: 3x3 conv -> offsets(18) + sigmoid(mask)(9), smem weights -
__global__ void __launch_bounds__(128) offmask_kernel() {
    __shared__ __align__(16) float wsm[16 * 9 * 32];  // 18KB: 16-ic chunk of g_wbT
    __shared__ __align__(16) float s[3][132];         // padded halo rows
    int tx = threadIdx.x;      // x coordinate
    int y  = blockIdx.x;       // row
    int b  = blockIdx.y;

    float acc[28];
#pragma unroll
    for (int j = 0; j < 28; j++) acc[j] = g_wbBias[j];

    const float* zb = g_z + (size_t)b * BNk * HWk;

#pragma unroll 1
    for (int ic0 = 0; ic0 < 64; ic0 += 16) {
        __syncthreads();
        const float4* wsrc = reinterpret_cast<const float4*>(g_wbT + ic0 * 9 * 32);
        float4* wdst = reinterpret_cast<float4*>(wsm);
#pragma unroll
        for (int j = tx; j < 16 * 9 * 8; j += 128) wdst[j] = wsrc[j];
        __syncthreads();

#pragma unroll 1
        for (int ici = 0; ici < 16; ici++) {
            const float* zp = zb + (size_t)(ic0 + ici) * HWk;
            __syncthreads();
#pragma unroll
            for (int dy = 0; dy < 3; dy++) {
                int yy = y + dy - 1;
                s[dy][tx + 1] = (yy >= 0 && yy < Hk) ? __ldg(zp + yy * Wk + tx) : 0.f;
            }
            if (tx == 0) {
                s[0][0] = 0.f; s[1][0] = 0.f; s[2][0] = 0.f;
                s[0][129] = 0.f; s[1][129] = 0.f; s[2][129] = 0.f;
            }
            __syncthreads();

#pragma unroll
            for (int tap = 0; tap < 9; tap++) {
                int ky = tap / 3, kx = tap % 3;
                float zv = s[ky][tx + kx];
                const float4* wrow = reinterpret_cast<const float4*>(wsm + (ici * 9 + tap) * 32);
#pragma unroll
                for (int j = 0; j < 7; j++) {
                    float4 w = wrow[j];
                    acc[4*j+0] += w.x * zv;
                    acc[4*j+1] += w.y * zv;
                    acc[4*j+2] += w.z * zv;
                    acc[4*j+3] += w.w * zv;
                }
            }
        }
    }

    int p = y * Wk + tx;
    float* offp = g_off + (size_t)b * 18 * HWk + p;
#pragma unroll
    for (int j = 0; j < 18; j++) offp[(size_t)j * HWk] = acc[j];
    float* mp = g_mask + (size_t)b * 9 * HWk + p;
#pragma unroll
    for (int j = 0; j < 9; j++)
        mp[(size_t)j * HWk] = 1.f / (1.f + __expf(-acc[18 + j]));
}

// -------- kernel C: deform conv (64ch out), oc half-split, smem weights -----
__global__ void __launch_bounds__(256) deform_kernel(const float* __restrict__ def_b) {
    __shared__ __align__(16) float wsm[64 * 64];   // 16KB: wd[k] chunk
    int tid  = threadIdx.x;
    int half = tid >> 7;
    int lpx  = tid & 127;
    int gp   = blockIdx.x * 128 + lpx;
    int b    = gp >> 14;
    int p    = gp & 16383;
    int y    = p >> 7;
    int x    = p & 127;

    const float* zb   = g_z    + (size_t)b * BNk * HWk;
    const float* offp = g_off  + (size_t)b * 18  * HWk + p;
    const float* mp   = g_mask + (size_t)b * 9   * HWk + p;

    float acc[32];
#pragma unroll
    for (int o = 0; o < 32; o++) acc[o] = __ldg(def_b + half * 32 + o);

#pragma unroll 1
    for (int k = 0; k < 9; k++) {
        __syncthreads();
        const float4* wk = reinterpret_cast<const float4*>(g_wdT + k * 4096);
        float4* wdst = reinterpret_cast<float4*>(wsm);
#pragma unroll
        for (int j = tid; j < 1024; j += 256) wdst[j] = wk[j];
        __syncthreads();

        int ky = k / 3, kx = k % 3;
        float dy = __ldg(offp + (size_t)(2 * k)     * HWk);
        float dx = __ldg(offp + (size_t)(2 * k + 1) * HWk);
        float mk = __ldg(mp   + (size_t)k           * HWk);

        float py = dy + (float)(y + ky - 1);
        float px = dx + (float)(x + kx - 1);
        float y0f = floorf(py), x0f = floorf(px);
        float wy = py - y0f, wx = px - x0f;
        int y0 = (int)y0f, x0 = (int)x0f;
        int y1 = y0 + 1,   x1 = x0 + 1;
        bool vy0 = (y0 >= 0) && (y0 < Hk), vy1 = (y1 >= 0) && (y1 < Hk);
        bool vx0 = (x0 >= 0) && (x0 < Wk), vx1 = (x1 >= 0) && (x1 < Wk);
        float a00 = (1.f - wy) * (1.f - wx) * mk * ((vy0 && vx0) ? 1.f : 0.f);
        float a01 = (1.f - wy) * wx         * mk * ((vy0 && vx1) ? 1.f : 0.f);
        float a10 = wy         * (1.f - wx) * mk * ((vy1 && vx0) ? 1.f : 0.f);
        float a11 = wy         * wx         * mk * ((vy1 && vx1) ? 1.f : 0.f);
        int yc0 = min(max(y0, 0), Hk - 1), yc1 = min(max(y1, 0), Hk - 1);
        int xc0 = min(max(x0, 0), Wk - 1), xc1 = min(max(x1, 0), Wk - 1);
        int i00 = yc0 * Wk + xc0, i01 = yc0 * Wk + xc1;
        int i10 = yc1 * Wk + xc0, i11 = yc1 * Wk + xc1;

#pragma unroll 4
        for (int c = 0; c < 64; c++) {
            const float* zc = zb + (size_t)c * HWk;
            float v = a00 * __ldg(zc + i00) + a01 * __ldg(zc + i01)
                    + a10 * __ldg(zc + i10) + a11 * __ldg(zc + i11);
            const float4* w4 = reinterpret_cast<const float4*>(wsm + c * 64 + half * 32);
#pragma unroll
            for (int j = 0; j < 8; j++) {
                float4 w = w4[j];
                acc[4*j+0] += w.x * v;
                acc[4*j+1] += w.y * v;
                acc[4*j+2] += w.z * v;
                acc[4*j+3] += w.w * v;
            }
        }
    }

    float* dp = g_d + (size_t)b * BNk * HWk + (size_t)half * 32 * HWk + p;
#pragma unroll
    for (int o = 0; o < 32; o++) dp[(size_t)o * HWk] = acc[o];
}

// -------- kernel D: 1x1 up conv + residual + BN stats ------------------------
__global__ void __launch_bounds__(128) up_kernel(const float* __restrict__ x,
                                                 const float* __restrict__ up_w,
                                                 float* __restrict__ out) {
    __shared__ __align__(16) float wsm[128 * 64];  // 32KB: up_w rows for this oc-half
    int tx = threadIdx.x;
    int gp = blockIdx.x * 128 + tx;
    int oh = blockIdx.y;               // oc half: 0/1
    int b  = gp >> 14;
    int p  = gp & 16383;

    const float4* wsrc = reinterpret_cast<const float4*>(up_w + oh * 128 * 64);
    float4* wdst = reinterpret_cast<float4*>(wsm);
#pragma unroll
    for (int j = tx; j < 2048; j += 128) wdst[j] = wsrc[j];
    __syncthreads();

    // load d[p][0..63] into registers (coalesced per channel plane)
    const float* dpb = g_d + (size_t)b * BNk * HWk + p;
    float dreg[64];
#pragma unroll
    for (int c = 0; c < 64; c++) dreg[c] = __ldg(dpb + (size_t)c * HWk);

    const float* xp = x   + (size_t)b * Ck * HWk + (size_t)oh * 128 * HWk + p;
    float*       op = out + (size_t)b * Ck * HWk + (size_t)oh * 128 * HWk + p;

#pragma unroll 1
    for (int oi = 0; oi < 128; oi++) {
        const float4* w4 = reinterpret_cast<const float4*>(wsm + oi * 64);
        float s0 = 0.f, s1 = 0.f, s2 = 0.f, s3 = 0.f;
#pragma unroll
        for (int j = 0; j < 16; j++) {
            float4 w = w4[j];
            s0 += w.x * dreg[4*j+0];
            s1 += w.y * dreg[4*j+1];
            s2 += w.z * dreg[4*j+2];
            s3 += w.w * dreg[4*j+3];
        }
        float yv = __ldg(xp + (size_t)oi * HWk) + ((s0 + s1) + (s2 + s3));
        op[(size_t)oi * HWk] = yv;

        float ws = yv, wq = yv * yv;
#pragma unroll
        for (int d = 16; d; d >>= 1) {
            ws += __shfl_xor_sync(0xffffffffu, ws, d);
            wq += __shfl_xor_sync(0xffffffffu, wq, d);
        }
        if ((tx & 31) == 0) {
            atomicAdd(&g_sum[oh * 128 + oi], ws);
            atomicAdd(&g_sumsq[oh * 128 + oi], wq);
        }
    }
}

// -------- kernel E: BatchNorm (training stats) + SiLU, in place --------
__global__ void __launch_bounds__(256) norm_kernel(float* __restrict__ out,
                                                   const float* __restrict__ gamma,
                                                   const float* __restrict__ beta) {
    const float invN = 1.f / (float)(Bk * HWk);   // 1/65536
    size_t i = (size_t)blockIdx.x * 256 + threadIdx.x;   // float4 index
    int ch = (int)((i >> 12) & 255);                      // 4096 float4 per channel

    float mean = g_sum[ch] * invN;
    float var  = g_sumsq[ch] * invN - mean * mean;
    float r    = rsqrtf(var + 1e-5f);
    float sc   = r * __ldg(gamma + ch);
    float sh   = __ldg(beta + ch) - mean * sc;

    float4* o4 = reinterpret_cast<float4*>(out);
    float4 v = o4[i];
    float h;
    h = v.x * sc + sh; v.x = h / (1.f + __expf(-h));
    h = v.y * sc + sh; v.y = h / (1.f + __expf(-h));
    h = v.z * sc + sh; v.z = h / (1.f + __expf(-h));
    h = v.w * sc + sh; v.w = h / (1.f + __expf(-h));
    o4[i] = v;
}

// -------- launch --------
extern "C" void kernel_launch(void* const* d_in, const int* in_sizes, int n_in,
                              void* d_out, int out_size) {
    const float* x      = (const float*)d_in[0];
    const float* down_w = (const float*)d_in[1];
    const float* off_w  = (const float*)d_in[2];
    const float* off_b  = (const float*)d_in[3];
    const float* mask_w = (const float*)d_in[4];
    const float* mask_b = (const float*)d_in[5];
    const float* def_w  = (const float*)d_in[6];
    const float* def_b  = (const float*)d_in[7];
    const float* up_w   = (const float*)d_in[8];
    const float* gamma  = (const float*)d_in[9];
    const float* beta   = (const float*)d_in[10];
    float* out = (float*)d_out;

    prep_kernel<<<144, 256>>>(down_w, off_w, off_b, mask_w, mask_b, def_w);
    down_kernel<<<512, 256>>>(x);
    offmask_kernel<<<dim3(Hk, Bk), 128>>>();
    deform_kernel<<<512, 256>>>(def_b);
    up_kernel<<<dim3(512, 2), 128>>>(x, up_w, out);
    norm_kernel<<<(Bk * Ck * HWk) / 4 / 256, 256>>>(out, gamma, beta);
}

// round 13
// speedup vs baseline: 2.0621x; 1.0940x over previous
#include <cuda_runtime.h>
#include <math.h>

// Problem constants
#define Bk   4
#define Ck   256
#define BNk  64
#define Hk   128
#define Wk   128
#define HWk  16384
#define K2k  9

// -------- scratch (device globals; no allocations allowed) --------
__device__ float g_z   [Bk * BNk * HWk];   // down-proj output (NCHW)
__device__ float g_d   [Bk * BNk * HWk];   // deform-conv output (NCHW)
__device__ float g_off [Bk * 18  * HWk];   // offsets
__device__ float g_mask[Bk * 9   * HWk];   // sigmoid(mask)
__device__ float g_dwT [Ck * BNk];         // down_w transposed: [c][o]
__device__ float g_wbT [BNk * 9 * 32];     // off/mask weights: [(ic*9+tap)*32 + oc], oc<27 valid
__device__ float g_wbBias[32];             // 18 off_b + 9 mask_b + pad
__device__ float g_wdT [9 * BNk * BNk];    // def_w: [(k*64+c)*64 + o]
__device__ float g_sum [Ck];
__device__ float g_sumsq[Ck];

// -------- prep: transpose/repack weights, zero stats --------
__global__ void prep_kernel(const float* __restrict__ down_w,
                            const float* __restrict__ off_w,
                            const float* __restrict__ off_b,
                            const float* __restrict__ mask_w,
                            const float* __restrict__ mask_b,
                            const float* __restrict__ def_w) {
    int i = blockIdx.x * 256 + threadIdx.x;
    if (i < Ck) { g_sum[i] = 0.f; g_sumsq[i] = 0.f; }
    if (i < Ck * BNk) {                 // down_w [64][256] -> [c][o]
        int o = i >> 8, c = i & 255;
        g_dwT[c * 64 + o] = down_w[i];
    }
    if (i < BNk * 9 * 32) {             // off/mask weights
        int oc = i & 31; int rest = i >> 5;
        int tap = rest % 9, ic = rest / 9;
        float v = 0.f;
        if (oc < 18)      v = off_w [(oc * 64 + ic) * 9 + tap];
        else if (oc < 27) v = mask_w[((oc - 18) * 64 + ic) * 9 + tap];
        g_wbT[i] = v;
    }
    if (i < 32) {
        float v = 0.f;
        if (i < 18)      v = off_b[i];
        else if (i < 27) v = mask_b[i - 18];
        g_wbBias[i] = v;
    }
    if (i < BNk * BNk * 9) {            // def_w [o][c][k] -> [(k*64+c)*64+o]
        int o = i / 576, rem = i % 576, c = rem / 9, k = rem % 9;
        g_wdT[(k * 64 + c) * 64 + o] = def_w[i];
    }
}

// -------- kernel A: 1x1 down conv (256->64), oc half-split, smem weights ----
__global__ void __launch_bounds__(256, 4) down_kernel(const float* __restrict__ x) {
    __shared__ __align__(16) float wsm[64 * 64];   // 16KB: chunk of dwT [c][64 oc]
    int tid  = threadIdx.x;
    int half = tid >> 7;               // 0/1 -> oc range
    int lpx  = tid & 127;
    int gp   = blockIdx.x * 128 + lpx; // global pixel incl. batch
    int b    = gp >> 14;
    int p    = gp & 16383;

    const float* xp = x + (size_t)b * Ck * HWk + p;

    float acc[32];
#pragma unroll
    for (int o = 0; o < 32; o++) acc[o] = 0.f;

    for (int c0 = 0; c0 < Ck; c0 += 64) {
        __syncthreads();
        const float4* wsrc = reinterpret_cast<const float4*>(g_dwT + c0 * 64);
        float4* wdst = reinterpret_cast<float4*>(wsm);
#pragma unroll
        for (int j = tid; j < 1024; j += 256) wdst[j] = wsrc[j];
        __syncthreads();

#pragma unroll 4
        for (int ci = 0; ci < 64; ci++) {
            float xv = __ldg(xp + (size_t)(c0 + ci) * HWk);
            const float4* w4 = reinterpret_cast<const float4*>(wsm + ci * 64 + half * 32);
#pragma unroll
            for (int j = 0; j < 8; j++) {
                float4 w = w4[j];
                acc[4*j+0] += w.x * xv;
                acc[4*j+1] += w.y * xv;
                acc[4*j+2] += w.z * xv;
                acc[4*j+3] += w.w * xv;
            }
        }
    }
    float* zp = g_z + (size_t)b * BNk * HWk + (size_t)half * 32 * HWk + p;
#pragma unroll
    for (int o = 0; o < 32; o++) zp[(size_t)o * HWk] = acc[o];
}

// -------- kernel B: 3x3 conv -> offsets(18) + sigmoid(mask)(9) --------------
// 2 rows per block, z halo staged per 8-ic chunk, weights staged per chunk.
__global__ void __launch_bounds__(256) offmask_kernel() {
    __shared__ __align__(16) float zs[8][4][132];   // 16.9KB halo: 8 ic x 4 rows
    __shared__ __align__(16) float wsm[8 * 9 * 32]; // 9.2KB weights chunk
    int tid = threadIdx.x;
    int r0  = tid >> 7;         // 0/1: which output row
    int tx  = tid & 127;        // x coordinate
    int by  = blockIdx.x;       // row pair: rows 2*by, 2*by+1
    int b   = blockIdx.y;
    int y   = by * 2 + r0;

    float acc[28];
#pragma unroll
    for (int j = 0; j < 28; j++) acc[j] = g_wbBias[j];

    const float* zb = g_z + (size_t)b * BNk * HWk;

#pragma unroll 1
    for (int ic0 = 0; ic0 < 64; ic0 += 8) {
        __syncthreads();
        // stage weights: 8*9*32 floats = 576 float4
        const float4* wsrc = reinterpret_cast<const float4*>(g_wbT + ic0 * 9 * 32);
        float4* wdst = reinterpret_cast<float4*>(wsm);
#pragma unroll
        for (int j = tid; j < 576; j += 256) wdst[j] = wsrc[j];
        // stage z halo: 8 ic x 4 rows x 128 cols
#pragma unroll
        for (int j = tid; j < 8 * 4 * 128; j += 256) {
            int ic = j >> 9;
            int r  = (j >> 7) & 3;
            int xx = j & 127;
            int yy = by * 2 + r - 1;
            zs[ic][r][xx + 1] = (yy >= 0 && yy < Hk)
                ? __ldg(zb + (size_t)(ic0 + ic) * HWk + yy * Wk + xx) : 0.f;
        }
        if (tid < 32) {
            int ic = tid >> 2, r = tid & 3;
            zs[ic][r][0] = 0.f; zs[ic][r][129] = 0.f;
        }
        __syncthreads();

#pragma unroll 1
        for (int ic = 0; ic < 8; ic++) {
#pragma unroll
            for (int tap = 0; tap < 9; tap++) {
                int ky = tap / 3, kx = tap % 3;
                float zv = zs[ic][r0 + ky][tx + kx];
                const float4* wrow = reinterpret_cast<const float4*>(wsm + (ic * 9 + tap) * 32);
#pragma unroll
                for (int j = 0; j < 7; j++) {
                    float4 w = wrow[j];
                    acc[4*j+0] += w.x * zv;
                    acc[4*j+1] += w.y * zv;
                    acc[4*j+2] += w.z * zv;
                    acc[4*j+3] += w.w * zv;
                }
            }
        }
    }

    int p = y * Wk + tx;
    float* offp = g_off + (size_t)b * 18 * HWk + p;
#pragma unroll
    for (int j = 0; j < 18; j++) offp[(size_t)j * HWk] = acc[j];
    float* mp = g_mask + (size_t)b * 9 * HWk + p;
#pragma unroll
    for (int j = 0; j < 9; j++)
        mp[(size_t)j * HWk] = 1.f / (1.f + __expf(-acc[18 + j]));
}

// -------- kernel C: deform conv (64ch out), half-split gather + smem v ------
__global__ void __launch_bounds__(256, 4) deform_kernel(const float* __restrict__ def_b) {
    __shared__ __align__(16) float wsm[64 * 64];    // 16KB: wd[k] chunk
    __shared__ __align__(16) float vsm[64][128];    // 32KB: sampled values
    int tid  = threadIdx.x;
    int half = tid >> 7;
    int tx   = tid & 127;
    int gp   = blockIdx.x * 128 + tx;
    int b    = gp >> 14;
    int p    = gp & 16383;
    int y    = p >> 7;
    int x    = p & 127;

    const float* zb   = g_z    + (size_t)b * BNk * HWk;
    const float* offp = g_off  + (size_t)b * 18  * HWk + p;
    const float* mp   = g_mask + (size_t)b * 9   * HWk + p;

    float acc[32];
#pragma unroll
    for (int o = 0; o < 32; o++) acc[o] = __ldg(def_b + half * 32 + o);

#pragma unroll 1
    for (int k = 0; k < 9; k++) {
        __syncthreads();   // previous tap's GEMM done before overwriting smem
        // stage this tap's weights
        const float4* wk4 = reinterpret_cast<const float4*>(g_wdT + k * 4096);
        float4* wdst = reinterpret_cast<float4*>(wsm);
#pragma unroll
        for (int j = tid; j < 1024; j += 256) wdst[j] = wk4[j];

        // bilinear coefficients (computed by both halves; cheap)
        int ky = k / 3, kx = k % 3;
        float dy = __ldg(offp + (size_t)(2 * k)     * HWk);
        float dx = __ldg(offp + (size_t)(2 * k + 1) * HWk);
        float mk = __ldg(mp   + (size_t)k           * HWk);

        float py = dy + (float)(y + ky - 1);
        float px = dx + (float)(x + kx - 1);
        float y0f = floorf(py), x0f = floorf(px);
        float wy = py - y0f, wx = px - x0f;
        int y0 = (int)y0f, x0 = (int)x0f;
        int y1 = y0 + 1,   x1 = x0 + 1;
        bool vy0 = (y0 >= 0) && (y0 < Hk), vy1 = (y1 >= 0) && (y1 < Hk);
        bool vx0 = (x0 >= 0) && (x0 < Wk), vx1 = (x1 >= 0) && (x1 < Wk);
        float a00 = (1.f - wy) * (1.f - wx) * mk * ((vy0 && vx0) ? 1.f : 0.f);
        float a01 = (1.f - wy) * wx         * mk * ((vy0 && vx1) ? 1.f : 0.f);
        float a10 = wy         * (1.f - wx) * mk * ((vy1 && vx0) ? 1.f : 0.f);
        float a11 = wy         * wx         * mk * ((vy1 && vx1) ? 1.f : 0.f);
        int yc0 = min(max(y0, 0), Hk - 1), yc1 = min(max(y1, 0), Hk - 1);
        int xc0 = min(max(x0, 0), Wk - 1), xc1 = min(max(x1, 0), Wk - 1);
        int i00 = yc0 * Wk + xc0, i01 = yc0 * Wk + xc1;
        int i10 = yc1 * Wk + xc0, i11 = yc1 * Wk + xc1;

        // half h gathers channels [h*32, h*32+32) for its pixel
        const float* zh = zb + (size_t)half * 32 * HWk;
#pragma unroll 4
        for (int c = 0; c < 32; c++) {
            const float* zc = zh + (size_t)c * HWk;
            float v = a00 * __ldg(zc + i00) + a01 * __ldg(zc + i01)
                    + a10 * __ldg(zc + i10) + a11 * __ldg(zc + i11);
            vsm[half * 32 + c][tx] = v;
        }
        __syncthreads();

        // GEMM over all 64 channels, this half's 32 output channels
#pragma unroll 2
        for (int c = 0; c < 64; c++) {
            float v = vsm[c][tx];
            const float4* w4 = reinterpret_cast<const float4*>(wsm + c * 64 + half * 32);
#pragma unroll
            for (int j = 0; j < 8; j++) {
                float4 w = w4[j];
                acc[4*j+0] += w.x * v;
                acc[4*j+1] += w.y * v;
                acc[4*j+2] += w.z * v;
                acc[4*j+3] += w.w * v;
            }
        }
    }

    float* dp = g_d + (size_t)b * BNk * HWk + (size_t)half * 32 * HWk + p;
#pragma unroll
    for (int o = 0; o < 32; o++) dp[(size_t)o * HWk] = acc[o];
}

// -------- kernel D: 1x1 up conv + residual + BN stats ------------------------
__global__ void __launch_bounds__(128) up_kernel(const float* __restrict__ x,
                                                 const float* __restrict__ up_w,
                                                 float* __restrict__ out) {
    __shared__ __align__(16) float wsm[128 * 64];  // 32KB: up_w rows for this oc-half
    int tx = threadIdx.x;
    int gp = blockIdx.x * 128 + tx;
    int oh = blockIdx.y;               // oc half: 0/1
    int b  = gp >> 14;
    int p  = gp & 16383;

    const float4* wsrc = reinterpret_cast<const float4*>(up_w + oh * 128 * 64);
    float4* wdst = reinterpret_cast<float4*>(wsm);
#pragma unroll
    for (int j = tx; j < 2048; j += 128) wdst[j] = wsrc[j];
    __syncthreads();

    // load d[p][0..63] into registers (coalesced per channel plane)
    const float* dpb = g_d + (size_t)b * BNk * HWk + p;
    float dreg[64];
#pragma unroll
    for (int c = 0; c < 64; c++) dreg[c] = __ldg(dpb + (size_t)c * HWk);

    const float* xp = x   + (size_t)b * Ck * HWk + (size_t)oh * 128 * HWk + p;
    float*       op = out + (size_t)b * Ck * HWk + (size_t)oh * 128 * HWk + p;

#pragma unroll 1
    for (int oi = 0; oi < 128; oi++) {
        const float4* w4 = reinterpret_cast<const float4*>(wsm + oi * 64);
        float s0 = 0.f, s1 = 0.f, s2 = 0.f, s3 = 0.f;
#pragma unroll
        for (int j = 0; j < 16; j++) {
            float4 w = w4[j];
            s0 += w.x * dreg[4*j+0];
            s1 += w.y * dreg[4*j+1];
            s2 += w.z * dreg[4*j+2];
            s3 += w.w * dreg[4*j+3];
        }
        float yv = __ldg(xp + (size_t)oi * HWk) + ((s0 + s1) + (s2 + s3));
        op[(size_t)oi * HWk] = yv;

        float ws = yv, wq = yv * yv;
#pragma unroll
        for (int d = 16; d; d >>= 1) {
            ws += __shfl_xor_sync(0xffffffffu, ws, d);
            wq += __shfl_xor_sync(0xffffffffu, wq, d);
        }
        if ((tx & 31) == 0) {
            atomicAdd(&g_sum[oh * 128 + oi], ws);
            atomicAdd(&g_sumsq[oh * 128 + oi], wq);
        }
    }
}

// -------- kernel E: BatchNorm (training stats) + SiLU, in place --------
__global__ void __launch_bounds__(256) norm_kernel(float* __restrict__ out,
                                                   const float* __restrict__ gamma,
                                                   const float* __restrict__ beta) {
    const float invN = 1.f / (float)(Bk * HWk);   // 1/65536
    size_t i = (size_t)blockIdx.x * 256 + threadIdx.x;   // float4 index
    int ch = (int)((i >> 12) & 255);                      // 4096 float4 per channel

    float mean = g_sum[ch] * invN;
    float var  = g_sumsq[ch] * invN - mean * mean;
    float r    = rsqrtf(var + 1e-5f);
    float sc   = r * __ldg(gamma + ch);
    float sh   = __ldg(beta + ch) - mean * sc;

    float4* o4 = reinterpret_cast<float4*>(out);
    float4 v = o4[i];
    float h;
    h = v.x * sc + sh; v.x = h / (1.f + __expf(-h));
    h = v.y * sc + sh; v.y = h / (1.f + __expf(-h));
    h = v.z * sc + sh; v.z = h / (1.f + __expf(-h));
    h = v.w * sc + sh; v.w = h / (1.f + __expf(-h));
    o4[i] = v;
}

// -------- launch --------
extern "C" void kernel_launch(void* const* d_in, const int* in_sizes, int n_in,
                              void* d_out, int out_size) {
    const float* x      = (const float*)d_in[0];
    const float* down_w = (const float*)d_in[1];
    const float* off_w  = (const float*)d_in[2];
    const float* off_b  = (const float*)d_in[3];
    const float* mask_w = (const float*)d_in[4];
    const float* mask_b = (const float*)d_in[5];
    const float* def_w  = (const float*)d_in[6];
    const float* def_b  = (const float*)d_in[7];
    const float* up_w   = (const float*)d_in[8];
    const float* gamma  = (const float*)d_in[9];
    const float* beta   = (const float*)d_in[10];
    float* out = (float*)d_out;

    prep_kernel<<<144, 256>>>(down_w, off_w, off_b, mask_w, mask_b, def_w);
    down_kernel<<<512, 256>>>(x);
    offmask_kernel<<<dim3(Hk / 2, Bk), 256>>>();
    deform_kernel<<<512, 256>>>(def_b);
    up_kernel<<<dim3(512, 2), 128>>>(x, up_w, out);
    norm_kernel<<<(Bk * Ck * HWk) / 4 / 256, 256>>>(out, gamma, beta);
}

// round 14
// speedup vs baseline: 3.8632x; 1.8735x over previous
#include <cuda_runtime.h>
#include <math.h>

typedef unsigned long long ull;

// Problem constants
#define Bk   4
#define Ck   256
#define BNk  64
#define Hk   128
#define Wk   128
#define HWk  16384
#define K2k  9

// -------- packed f32x2 helpers (Blackwell FFMA2) --------
__device__ __forceinline__ void ffma2(ull& d, ull a, ull b) {
    asm("fma.rn.f32x2 %0, %1, %2, %0;" : "+l"(d) : "l"(a), "l"(b));
}
__device__ __forceinline__ ull pack2(float v) {
    ull r; asm("mov.b64 %0, {%1, %1};" : "=l"(r) : "f"(v)); return r;
}
__device__ __forceinline__ ull pack2(float a, float b) {
    ull r; asm("mov.b64 %0, {%1, %2};" : "=l"(r) : "f"(a), "f"(b)); return r;
}
__device__ __forceinline__ float2 unpack2(ull v) {
    float2 f; asm("mov.b64 {%0, %1}, %2;" : "=f"(f.x), "=f"(f.y) : "l"(v)); return f;
}

// -------- scratch (device globals; no allocations allowed) --------
__device__ float g_z   [Bk * BNk * HWk];   // down-proj output (NCHW)
__device__ float g_d   [Bk * BNk * HWk];   // deform-conv output (NCHW)
__device__ float g_off [Bk * 18  * HWk];   // offsets
__device__ float g_mask[Bk * 9   * HWk];   // sigmoid(mask)
__device__ float g_dwT [Ck * BNk];         // down_w transposed: [c][o]
__device__ float g_uwT [BNk * Ck];         // up_w transposed: [c][oc]
__device__ float g_wbT [BNk * 9 * 32];     // off/mask weights: [(ic*9+tap)*32 + oc]
__device__ float g_wbBias[32];             // 18 off_b + 9 mask_b + pad
__device__ float g_wdT [9 * BNk * BNk];    // def_w: [(k*64+c)*64 + o]
__device__ float g_sum [Ck];
__device__ float g_sumsq[Ck];

// -------- prep: transpose/repack weights, zero stats --------
__global__ void prep_kernel(const float* __restrict__ down_w,
                            const float* __restrict__ off_w,
                            const float* __restrict__ off_b,
                            const float* __restrict__ mask_w,
                            const float* __restrict__ mask_b,
                            const float* __restrict__ def_w,
                            const float* __restrict__ up_w) {
    int i = blockIdx.x * 256 + threadIdx.x;
    if (i < Ck) { g_sum[i] = 0.f; g_sumsq[i] = 0.f; }
    if (i < Ck * BNk) {                 // down_w [64][256] -> [c][o]
        int o = i >> 8, c = i & 255;
        g_dwT[c * 64 + o] = down_w[i];
        // up_w [256][64] -> [c][oc]
        int oc = i >> 6, cc = i & 63;
        g_uwT[cc * 256 + oc] = up_w[i];
    }
    if (i < BNk * 9 * 32) {             // off/mask weights
        int oc = i & 31; int rest = i >> 5;
        int tap = rest % 9, ic = rest / 9;
        float v = 0.f;
        if (oc < 18)      v = off_w [(oc * 64 + ic) * 9 + tap];
        else if (oc < 27) v = mask_w[((oc - 18) * 64 + ic) * 9 + tap];
        g_wbT[i] = v;
    }
    if (i < 32) {
        float v = 0.f;
        if (i < 18)      v = off_b[i];
        else if (i < 27) v = mask_b[i - 18];
        g_wbBias[i] = v;
    }
    if (i < BNk * BNk * 9) {            // def_w [o][c][k] -> [(k*64+c)*64+o]
        int o = i / 576, rem = i % 576, c = rem / 9, k = rem % 9;
        g_wdT[(k * 64 + c) * 64 + o] = def_w[i];
    }
}

// -------- kernel A: 1x1 down conv (256->64), 4px x 8oc register tile --------
__global__ void __launch_bounds__(256, 4) down_kernel(const float* __restrict__ x) {
    __shared__ __align__(16) float wsm[64 * 64];    // 16KB: 64-c chunk of dwT
    __shared__ __align__(16) float xsm[64][128];    // 32KB: x tile
    int tid = threadIdx.x;
    int og  = tid >> 5;                // oc group: 8 channels [og*8, og*8+8)
    int q   = tid & 31;                // pixel lane: px {q, q+32, q+64, q+96}
    int bp  = blockIdx.x * 128;
    int b   = bp >> 14;
    int p0  = bp & 16383;

    ull acc2[4][4];
#pragma unroll
    for (int j = 0; j < 4; j++)
#pragma unroll
        for (int o2 = 0; o2 < 4; o2++) acc2[j][o2] = 0ull;

    const float* xb = x + (size_t)b * Ck * HWk + p0;

    for (int c0 = 0; c0 < Ck; c0 += 64) {
        __syncthreads();
        {   // stage weights: 1024 float4
            const float4* wsrc = reinterpret_cast<const float4*>(g_dwT + c0 * 64);
            float4* wdst = reinterpret_cast<float4*>(wsm);
#pragma unroll
            for (int j = tid; j < 1024; j += 256) wdst[j] = wsrc[j];
        }
        {   // stage x tile: 64 ch x 128 px = 2048 float4
            float4* xd = reinterpret_cast<float4*>(&xsm[0][0]);
#pragma unroll
            for (int j = tid; j < 2048; j += 256) {
                int c = j >> 5, x4 = j & 31;
                xd[j] = *reinterpret_cast<const float4*>(xb + (size_t)(c0 + c) * HWk + x4 * 4);
            }
        }
        __syncthreads();

#pragma unroll 2
        for (int ci = 0; ci < 64; ci++) {
            ull vp0 = pack2(xsm[ci][q]);
            ull vp1 = pack2(xsm[ci][q + 32]);
            ull vp2 = pack2(xsm[ci][q + 64]);
            ull vp3 = pack2(xsm[ci][q + 96]);
            const ulonglong2* wp = reinterpret_cast<const ulonglong2*>(wsm + ci * 64 + og * 8);
            ulonglong2 wa = wp[0], wb = wp[1];
            ffma2(acc2[0][0], wa.x, vp0); ffma2(acc2[0][1], wa.y, vp0);
            ffma2(acc2[0][2], wb.x, vp0); ffma2(acc2[0][3], wb.y, vp0);
            ffma2(acc2[1][0], wa.x, vp1); ffma2(acc2[1][1], wa.y, vp1);
            ffma2(acc2[1][2], wb.x, vp1); ffma2(acc2[1][3], wb.y, vp1);
            ffma2(acc2[2][0], wa.x, vp2); ffma2(acc2[2][1], wa.y, vp2);
            ffma2(acc2[2][2], wb.x, vp2); ffma2(acc2[2][3], wb.y, vp2);
            ffma2(acc2[3][0], wa.x, vp3); ffma2(acc2[3][1], wa.y, vp3);
            ffma2(acc2[3][2], wb.x, vp3); ffma2(acc2[3][3], wb.y, vp3);
        }
    }

    float* zb = g_z + (size_t)b * BNk * HWk + p0;
#pragma unroll
    for (int j = 0; j < 4; j++) {
        int p = q + 32 * j;
#pragma unroll
        for (int o2 = 0; o2 < 4; o2++) {
            float2 f = unpack2(acc2[j][o2]);
            zb[(size_t)(og * 8 + 2 * o2)     * HWk + p] = f.x;
            zb[(size_t)(og * 8 + 2 * o2 + 1) * HWk + p] = f.y;
        }
    }
}

// -------- kernel B: 3x3 conv -> offsets(18) + sigmoid(mask)(9), f32x2 -------
__global__ void __launch_bounds__(256) offmask_kernel() {
    __shared__ __align__(16) float zs[8][4][132];   // halo: 8 ic x 4 rows
    __shared__ __align__(16) float wsm[8 * 9 * 32]; // weights chunk
    int tid = threadIdx.x;
    int r0  = tid >> 7;         // 0/1: which output row
    int tx  = tid & 127;        // x coordinate
    int by  = blockIdx.x;       // row pair
    int b   = blockIdx.y;
    int y   = by * 2 + r0;

    ull acc2[14];
#pragma unroll
    for (int j = 0; j < 14; j++) acc2[j] = pack2(g_wbBias[2 * j], g_wbBias[2 * j + 1]);

    const float* zb = g_z + (size_t)b * BNk * HWk;

#pragma unroll 1
    for (int ic0 = 0; ic0 < 64; ic0 += 8) {
        __syncthreads();
        const float4* wsrc = reinterpret_cast<const float4*>(g_wbT + ic0 * 9 * 32);
        float4* wdst = reinterpret_cast<float4*>(wsm);
#pragma unroll
        for (int j = tid; j < 576; j += 256) wdst[j] = wsrc[j];
#pragma unroll
        for (int j = tid; j < 8 * 4 * 128; j += 256) {
            int ic = j >> 9;
            int r  = (j >> 7) & 3;
            int xx = j & 127;
            int yy = by * 2 + r - 1;
            zs[ic][r][xx + 1] = (yy >= 0 && yy < Hk)
                ? __ldg(zb + (size_t)(ic0 + ic) * HWk + yy * Wk + xx) : 0.f;
        }
        if (tid < 32) {
            int ic = tid >> 2, r = tid & 3;
            zs[ic][r][0] = 0.f; zs[ic][r][129] = 0.f;
        }
        __syncthreads();

#pragma unroll 1
        for (int ic = 0; ic < 8; ic++) {
#pragma unroll
            for (int tap = 0; tap < 9; tap++) {
                int ky = tap / 3, kx = tap % 3;
                ull zp = pack2(zs[ic][r0 + ky][tx + kx]);
                const ulonglong2* w2 = reinterpret_cast<const ulonglong2*>(wsm + (ic * 9 + tap) * 32);
                ulonglong2 wA = w2[0], wB = w2[1], wC = w2[2], wD = w2[3];
                ulonglong2 wE = w2[4], wF = w2[5], wG = w2[6];
                ffma2(acc2[0],  wA.x, zp); ffma2(acc2[1],  wA.y, zp);
                ffma2(acc2[2],  wB.x, zp); ffma2(acc2[3],  wB.y, zp);
                ffma2(acc2[4],  wC.x, zp); ffma2(acc2[5],  wC.y, zp);
                ffma2(acc2[6],  wD.x, zp); ffma2(acc2[7],  wD.y, zp);
                ffma2(acc2[8],  wE.x, zp); ffma2(acc2[9],  wE.y, zp);
                ffma2(acc2[10], wF.x, zp); ffma2(acc2[11], wF.y, zp);
                ffma2(acc2[12], wG.x, zp); ffma2(acc2[13], wG.y, zp);
            }
        }
    }

    int p = y * Wk + tx;
    float* offp = g_off + (size_t)b * 18 * HWk + p;
#pragma unroll
    for (int j = 0; j < 9; j++) {
        float2 f = unpack2(acc2[j]);
        offp[(size_t)(2 * j)     * HWk] = f.x;
        offp[(size_t)(2 * j + 1) * HWk] = f.y;
    }
    float* mp = g_mask + (size_t)b * 9 * HWk + p;
#pragma unroll
    for (int j = 9; j < 14; j++) {
        float2 f = unpack2(acc2[j]);
        int m = 2 * j - 18;
        mp[(size_t)m * HWk] = 1.f / (1.f + __expf(-f.x));
        if (m + 1 < 9) mp[(size_t)(m + 1) * HWk] = 1.f / (1.f + __expf(-f.y));
    }
}

// -------- kernel C: deform conv, half-split gather + 4px x 8oc tile ---------
__global__ void __launch_bounds__(256, 4) deform_kernel(const float* __restrict__ def_b) {
    __shared__ __align__(16) float wsm[64 * 64];    // 16KB: wd[k] chunk
    __shared__ __align__(16) float vsm[64][128];    // 32KB: sampled values
    int tid  = threadIdx.x;
    int half = tid >> 7;        // gather role
    int tx   = tid & 127;
    int og   = tid >> 5;        // GEMM role: 8 oc
    int q    = tid & 31;        // GEMM pixel lane
    int bp   = blockIdx.x * 128;
    int b    = bp >> 14;
    int p0   = bp & 16383;
    int gy   = (p0 + tx) >> 7;
    int gx   = (p0 + tx) & 127;

    const float* zb   = g_z    + (size_t)b * BNk * HWk;
    const float* offp = g_off  + (size_t)b * 18  * HWk + p0 + tx;
    const float* mp   = g_mask + (size_t)b * 9   * HWk + p0 + tx;

    ull acc2[4][4];
#pragma unroll
    for (int o2 = 0; o2 < 4; o2++) {
        ull bb = pack2(__ldg(def_b + og * 8 + 2 * o2), __ldg(def_b + og * 8 + 2 * o2 + 1));
#pragma unroll
        for (int j = 0; j < 4; j++) acc2[j][o2] = bb;
    }

#pragma unroll 1
    for (int k = 0; k < 9; k++) {
        __syncthreads();   // previous tap's GEMM done before overwriting smem
        {   // stage this tap's weights
            const float4* wk4 = reinterpret_cast<const float4*>(g_wdT + k * 4096);
            float4* wdst = reinterpret_cast<float4*>(wsm);
#pragma unroll
            for (int j = tid; j < 1024; j += 256) wdst[j] = wk4[j];
        }

        // bilinear gather: half h handles channels [h*32, h*32+32) for pixel tx
        {
            int ky = k / 3, kx = k % 3;
            float dy = __ldg(offp + (size_t)(2 * k)     * HWk);
            float dx = __ldg(offp + (size_t)(2 * k + 1) * HWk);
            float mk = __ldg(mp   + (size_t)k           * HWk);

            float py = dy + (float)(gy + ky - 1);
            float px = dx + (float)(gx + kx - 1);
            float y0f = floorf(py), x0f = floorf(px);
            float wy = py - y0f, wx = px - x0f;
            int y0 = (int)y0f, x0 = (int)x0f;
            int y1 = y0 + 1,   x1 = x0 + 1;
            bool vy0 = (y0 >= 0) && (y0 < Hk), vy1 = (y1 >= 0) && (y1 < Hk);
            bool vx0 = (x0 >= 0) && (x0 < Wk), vx1 = (x1 >= 0) && (x1 < Wk);
            float a00 = (1.f - wy) * (1.f - wx) * mk * ((vy0 && vx0) ? 1.f : 0.f);
            float a01 = (1.f - wy) * wx         * mk * ((vy0 && vx1) ? 1.f : 0.f);
            float a10 = wy         * (1.f - wx) * mk * ((vy1 && vx0) ? 1.f : 0.f);
            float a11 = wy         * wx         * mk * ((vy1 && vx1) ? 1.f : 0.f);
            int yc0 = min(max(y0, 0), Hk - 1), yc1 = min(max(y1, 0), Hk - 1);
            int xc0 = min(max(x0, 0), Wk - 1), xc1 = min(max(x1, 0), Wk - 1);
            int i00 = yc0 * Wk + xc0, i01 = yc0 * Wk + xc1;
            int i10 = yc1 * Wk + xc0, i11 = yc1 * Wk + xc1;

            const float* zh = zb + (size_t)half * 32 * HWk;
#pragma unroll 4
            for (int c = 0; c < 32; c++) {
                const float* zc = zh + (size_t)c * HWk;
                float v = a00 * __ldg(zc + i00) + a01 * __ldg(zc + i01)
                        + a10 * __ldg(zc + i10) + a11 * __ldg(zc + i11);
                vsm[half * 32 + c][tx] = v;
            }
        }
        __syncthreads();

        // GEMM: 64 c-steps, each thread 4 px x 8 oc via FFMA2
#pragma unroll 2
        for (int c = 0; c < 64; c++) {
            ull vp0 = pack2(vsm[c][q]);
            ull vp1 = pack2(vsm[c][q + 32]);
            ull vp2 = pack2(vsm[c][q + 64]);
            ull vp3 = pack2(vsm[c][q + 96]);
            const ulonglong2* wp = reinterpret_cast<const ulonglong2*>(wsm + c * 64 + og * 8);
            ulonglong2 wa = wp[0], wb = wp[1];
            ffma2(acc2[0][0], wa.x, vp0); ffma2(acc2[0][1], wa.y, vp0);
            ffma2(acc2[0][2], wb.x, vp0); ffma2(acc2[0][3], wb.y, vp0);
            ffma2(acc2[1][0], wa.x, vp1); ffma2(acc2[1][1], wa.y, vp1);
            ffma2(acc2[1][2], wb.x, vp1); ffma2(acc2[1][3], wb.y, vp1);
            ffma2(acc2[2][0], wa.x, vp2); ffma2(acc2[2][1], wa.y, vp2);
            ffma2(acc2[2][2], wb.x, vp2); ffma2(acc2[2][3], wb.y, vp2);
            ffma2(acc2[3][0], wa.x, vp3); ffma2(acc2[3][1], wa.y, vp3);
            ffma2(acc2[3][2], wb.x, vp3); ffma2(acc2[3][3], wb.y, vp3);
        }
    }

    float* dbp = g_d + (size_t)b * BNk * HWk + p0;
#pragma unroll
    for (int j = 0; j < 4; j++) {
        int p = q + 32 * j;
#pragma unroll
        for (int o2 = 0; o2 < 4; o2++) {
            float2 f = unpack2(acc2[j][o2]);
            dbp[(size_t)(og * 8 + 2 * o2)     * HWk + p] = f.x;
            dbp[(size_t)(og * 8 + 2 * o2 + 1) * HWk + p] = f.y;
        }
    }
}

// -------- kernel D: 1x1 up conv + residual + BN stats, 4px x 8oc tile -------
__global__ void __launch_bounds__(256, 4) up_kernel(const float* __restrict__ x,
                                                    float* __restrict__ out) {
    __shared__ __align__(16) float wsm[64 * 64];   // 16KB: uwT chunk [c][64 oc]
    __shared__ __align__(16) float dsm[64][128];   // 32KB: d tile
    int tid = threadIdx.x;
    int og  = tid >> 5;
    int q   = tid & 31;
    int oh  = blockIdx.y;             // oc quarter: [oh*64, oh*64+64)
    int bp  = blockIdx.x * 128;
    int b   = bp >> 14;
    int p0  = bp & 16383;

    {   // stage weights: wsm[c][oi] = g_uwT[c*256 + oh*64 + oi]
        const float4* usrc = reinterpret_cast<const float4*>(g_uwT);
        float4* wdst = reinterpret_cast<float4*>(wsm);
#pragma unroll
        for (int j = tid; j < 1024; j += 256) {
            int c = j >> 4, o4 = j & 15;
            wdst[j] = usrc[c * 64 + oh * 16 + o4];
        }
    }
    {   // stage d tile
        const float* db = g_d + (size_t)b * BNk * HWk + p0;
        float4* dd = reinterpret_cast<float4*>(&dsm[0][0]);
#pragma unroll
        for (int j = tid; j < 2048; j += 256) {
            int c = j >> 5, x4 = j & 31;
            dd[j] = *reinterpret_cast<const float4*>(db + (size_t)c * HWk + x4 * 4);
        }
    }
    __syncthreads();

    ull acc2[4][4];
#pragma unroll
    for (int j = 0; j < 4; j++)
#pragma unroll
        for (int o2 = 0; o2 < 4; o2++) acc2[j][o2] = 0ull;

#pragma unroll 2
    for (int c = 0; c < 64; c++) {
        ull vp0 = pack2(dsm[c][q]);
        ull vp1 = pack2(dsm[c][q + 32]);
        ull vp2 = pack2(dsm[c][q + 64]);
        ull vp3 = pack2(dsm[c][q + 96]);
        const ulonglong2* wp = reinterpret_cast<const ulonglong2*>(wsm + c * 64 + og * 8);
        ulonglong2 wa = wp[0], wb = wp[1];
        ffma2(acc2[0][0], wa.x, vp0); ffma2(acc2[0][1], wa.y, vp0);
        ffma2(acc2[0][2], wb.x, vp0); ffma2(acc2[0][3], wb.y, vp0);
        ffma2(acc2[1][0], wa.x, vp1); ffma2(acc2[1][1], wa.y, vp1);
        ffma2(acc2[1][2], wb.x, vp1); ffma2(acc2[1][3], wb.y, vp1);
        ffma2(acc2[2][0], wa.x, vp2); ffma2(acc2[2][1], wa.y, vp2);
        ffma2(acc2[2][2], wb.x, vp2); ffma2(acc2[2][3], wb.y, vp2);
        ffma2(acc2[3][0], wa.x, vp3); ffma2(acc2[3][1], wa.y, vp3);
        ffma2(acc2[3][2], wb.x, vp3); ffma2(acc2[3][3], wb.y, vp3);
    }

    // epilogue: +x, write, BN partial sums (warp covers all 128 px of block)
    const float* xb = x   + (size_t)b * Ck * HWk + p0;
    float*       ob = out + (size_t)b * Ck * HWk + p0;
#pragma unroll
    for (int o2 = 0; o2 < 4; o2++) {
        int oc0 = oh * 64 + og * 8 + 2 * o2;
        float ws0 = 0.f, wq0 = 0.f, ws1 = 0.f, wq1 = 0.f;
#pragma unroll
        for (int j = 0; j < 4; j++) {
            int p = q + 32 * j;
            float2 f = unpack2(acc2[j][o2]);
            float y0 = __ldg(xb + (size_t)oc0 * HWk + p) + f.x;
            float y1 = __ldg(xb + (size_t)(oc0 + 1) * HWk + p) + f.y;
            ob[(size_t)oc0       * HWk + p] = y0;
            ob[(size_t)(oc0 + 1) * HWk + p] = y1;
            ws0 += y0; wq0 += y0 * y0;
            ws1 += y1; wq1 += y1 * y1;
        }
#pragma unroll
        for (int d = 16; d; d >>= 1) {
            ws0 += __shfl_xor_sync(0xffffffffu, ws0, d);
            wq0 += __shfl_xor_sync(0xffffffffu, wq0, d);
            ws1 += __shfl_xor_sync(0xffffffffu, ws1, d);
            wq1 += __shfl_xor_sync(0xffffffffu, wq1, d);
        }
        if (q == 0) {
            atomicAdd(&g_sum[oc0],       ws0);
            atomicAdd(&g_sumsq[oc0],     wq0);
            atomicAdd(&g_sum[oc0 + 1],   ws1);
            atomicAdd(&g_sumsq[oc0 + 1], wq1);
        }
    }
}

// -------- kernel E: BatchNorm (training stats) + SiLU, in place --------
__global__ void __launch_bounds__(256) norm_kernel(float* __restrict__ out,
                                                   const float* __restrict__ gamma,
                                                   const float* __restrict__ beta) {
    const float invN = 1.f / (float)(Bk * HWk);   // 1/65536
    size_t i = (size_t)blockIdx.x * 256 + threadIdx.x;   // float4 index
    int ch = (int)((i >> 12) & 255);                      // 4096 float4 per channel

    float mean = g_sum[ch] * invN;
    float var  = g_sumsq[ch] * invN - mean * mean;
    float r    = rsqrtf(var + 1e-5f);
    float sc   = r * __ldg(gamma + ch);
    float sh   = __ldg(beta + ch) - mean * sc;

    float4* o4 = reinterpret_cast<float4*>(out);
    float4 v = o4[i];
    float h;
    h = v.x * sc + sh; v.x = h / (1.f + __expf(-h));
    h = v.y * sc + sh; v.y = h / (1.f + __expf(-h));
    h = v.z * sc + sh; v.z = h / (1.f + __expf(-h));
    h = v.w * sc + sh; v.w = h / (1.f + __expf(-h));
    o4[i] = v;
}

// -------- launch --------
extern "C" void kernel_launch(void* const* d_in, const int* in_sizes, int n_in,
                              void* d_out, int out_size) {
    const float* x      = (const float*)d_in[0];
    const float* down_w = (const float*)d_in[1];
    const float* off_w  = (const float*)d_in[2];
    const float* off_b  = (const float*)d_in[3];
    const float* mask_w = (const float*)d_in[4];
    const float* mask_b = (const float*)d_in[5];
    const float* def_w  = (const float*)d_in[6];
    const float* def_b  = (const float*)d_in[7];
    const float* up_w   = (const float*)d_in[8];
    const float* gamma  = (const float*)d_in[9];
    const float* beta   = (const float*)d_in[10];
    float* out = (float*)d_out;

    prep_kernel<<<144, 256>>>(down_w, off_w, off_b, mask_w, mask_b, def_w, up_w);
    down_kernel<<<512, 256>>>(x);
    offmask_kernel<<<dim3(Hk / 2, Bk), 256>>>();
    deform_kernel<<<512, 256>>>(def_b);
    up_kernel<<<dim3(512, 4), 256>>>(x, out);
    norm_kernel<<<(Bk * Ck * HWk) / 4 / 256, 256>>>(out, gamma, beta);
}